// round 1
// baseline (speedup 1.0000x reference)
#include <cuda_runtime.h>
#include <math.h>

#define N_NODES 65536
#define N_EDGES 524288
#define C 128
#define L 3
#define BN_EPS 1e-5f

// ---------------- scratch (device globals; no dynamic allocation) ----------------
__device__ float  g_h[N_NODES * C];       // layer output (ping buffer)
__device__ float  g_hn[N_NODES * C];      // batch-normalized activations
__device__ float  g_neigh[N_NODES * C];   // aggregated neighbor features (already /deg)
__device__ float2 g_edge[N_EDGES];        // CSR-by-dst packed records: (src as int bits, log1p(w))
__device__ int    g_degcnt[N_NODES];
__device__ int    g_off[N_NODES + 1];
__device__ int    g_cursor[N_NODES];
__device__ float  g_deginv[N_NODES];
__device__ float  g_stats[L * 2 * C];     // per-layer [sum(C) | sumsq(C)]

// ---------------- prep: zero counters/stats ----------------
__global__ void k_prep0() {
    int i = blockIdx.x * blockDim.x + threadIdx.x;   // 65536 threads
    if (i < N_NODES) g_degcnt[i] = 0;
    if (i < L * 2 * C) g_stats[i] = 0.0f;
}

// ---------------- prep: in-degree histogram ----------------
__global__ void k_count(const int* __restrict__ dst) {
    int e = blockIdx.x * blockDim.x + threadIdx.x;
    if (e < N_EDGES) atomicAdd(&g_degcnt[dst[e]], 1);
}

// ---------------- prep: exclusive scan over 65536 counts (single block) ----------------
__global__ void k_scan() {
    __shared__ int sp[1024];
    int t = threadIdx.x;                   // 1024 threads, 64 counts each
    int base = t * 64;
    int sum = 0;
    #pragma unroll 4
    for (int i = 0; i < 64; i++) sum += g_degcnt[base + i];
    sp[t] = sum;
    __syncthreads();
    // Hillis-Steele inclusive scan over 1024 partials
    for (int o = 1; o < 1024; o <<= 1) {
        int v = (t >= o) ? sp[t - o] : 0;
        __syncthreads();
        sp[t] += v;
        __syncthreads();
    }
    int run = sp[t] - sum;                 // exclusive prefix for this chunk
    for (int i = 0; i < 64; i++) {
        int cnt = g_degcnt[base + i];
        g_off[base + i] = run;
        g_cursor[base + i] = run;
        g_deginv[base + i] = 1.0f / fmaxf((float)cnt, 1.0f);
        run += cnt;
    }
    if (t == 1023) g_off[N_NODES] = run;   // == N_EDGES
}

// ---------------- prep: scatter edges into CSR order, pack (src, log1p(w)) ----------------
__global__ void k_scatter(const int* __restrict__ src, const int* __restrict__ dst,
                          const float* __restrict__ ew) {
    int e = blockIdx.x * blockDim.x + threadIdx.x;
    if (e >= N_EDGES) return;
    int p = atomicAdd(&g_cursor[dst[e]], 1);
    g_edge[p] = make_float2(__int_as_float(src[e]), log1pf(ew[e]));
}

// ---------------- per-layer: BN column sums ----------------
__global__ void k_stats(const float* __restrict__ x, int l) {
    const float* hp = (l == 0) ? x : g_h;
    int tid = threadIdx.x;                 // 256 threads
    int c = tid & (C - 1);
    int rr = tid >> 7;                     // 0..1
    float s = 0.0f, s2 = 0.0f;
    for (int r = blockIdx.x * 2 + rr; r < N_NODES; r += gridDim.x * 2) {
        float v = hp[(size_t)r * C + c];
        s += v; s2 += v * v;
    }
    atomicAdd(&g_stats[l * 2 * C + c], s);
    atomicAdd(&g_stats[l * 2 * C + C + c], s2);
}

// ---------------- per-layer: normalize into g_hn ----------------
__global__ void k_norm(const float* __restrict__ x, const float* __restrict__ gamma,
                       const float* __restrict__ beta, int l) {
    __shared__ float sscale[C], sshift[C];
    const float* hp = (l == 0) ? x : g_h;
    int tid = threadIdx.x;                 // 256 threads
    if (tid < C) {
        float sum = g_stats[l * 2 * C + tid];
        float sq  = g_stats[l * 2 * C + C + tid];
        float mu  = sum * (1.0f / N_NODES);
        float var = sq * (1.0f / N_NODES) - mu * mu;
        float sc  = gamma[tid] * rsqrtf(var + BN_EPS);
        sscale[tid] = sc;
        sshift[tid] = beta[tid] - mu * sc;
    }
    __syncthreads();
    const float4* in4 = (const float4*)hp;
    float4* out4 = (float4*)g_hn;
    int total4 = N_NODES * C / 4;
    for (int i = blockIdx.x * blockDim.x + tid; i < total4; i += gridDim.x * blockDim.x) {
        int c4 = (i & 31) * 4;
        float4 v = in4[i];
        v.x = v.x * sscale[c4 + 0] + sshift[c4 + 0];
        v.y = v.y * sscale[c4 + 1] + sshift[c4 + 1];
        v.z = v.z * sscale[c4 + 2] + sshift[c4 + 2];
        v.w = v.w * sscale[c4 + 3] + sshift[c4 + 3];
        out4[i] = v;
    }
}

// ---------------- per-layer: mean aggregation, warp per node, no atomics ----------------
__global__ void k_aggr() {
    int n = (blockIdx.x * blockDim.x + threadIdx.x) >> 5;
    int lane = threadIdx.x & 31;
    if (n >= N_NODES) return;
    int beg = g_off[n], end = g_off[n + 1];
    const float4* hn4 = (const float4*)g_hn;
    float4 acc = make_float4(0.f, 0.f, 0.f, 0.f);
    for (int i = beg; i < end; i++) {
        float2 srw = g_edge[i];            // broadcast load (all lanes same addr)
        int s = __float_as_int(srw.x);
        float w = srw.y;
        float4 v = hn4[(size_t)s * 32 + lane];
        acc.x += w * v.x; acc.y += w * v.y; acc.z += w * v.z; acc.w += w * v.w;
    }
    float di = g_deginv[n];
    acc.x *= di; acc.y *= di; acc.z *= di; acc.w *= di;
    ((float4*)g_neigh)[(size_t)n * 32 + lane] = acc;
}

// ---------------- per-layer: fused dual GEMM (K=256) + bias + ReLU ----------------
// out = relu([hn | neigh] @ [Ws ; Wn] + bias), tile 128x128, BK=16, 256 thr, 8x8 micro
__global__ __launch_bounds__(256, 2)
void k_gemm(const float* __restrict__ Ws, const float* __restrict__ Wn,
            const float* __restrict__ bias) {
    __shared__ float As[16][C];
    __shared__ float Bs[16][C];
    int tid = threadIdx.x;
    int tx = tid & 15, ty = tid >> 4;
    int row0 = blockIdx.x * 128;

    float acc[8][8];
    #pragma unroll
    for (int i = 0; i < 8; i++)
        #pragma unroll
        for (int j = 0; j < 8; j++) acc[i][j] = 0.0f;

    for (int kt = 0; kt < 2 * C; kt += 16) {
        int second = (kt >= C);
        int kb = second ? kt - C : kt;
        const float* Asrc = second ? g_neigh : g_hn;
        const float* Wsrc = second ? Wn : Ws;
        __syncthreads();
        #pragma unroll
        for (int hh = 0; hh < 2; hh++) {       // A tile: 128x16
            int f = tid + hh * 256;
            int m = f >> 2;
            int kq = (f & 3) << 2;
            float4 v = *(const float4*)(Asrc + (size_t)(row0 + m) * C + kb + kq);
            As[kq + 0][m] = v.x; As[kq + 1][m] = v.y;
            As[kq + 2][m] = v.z; As[kq + 3][m] = v.w;
        }
        #pragma unroll
        for (int hh = 0; hh < 2; hh++) {       // B tile: 16x128
            int f = tid + hh * 256;
            int kk = f >> 5;
            int c = (f & 31) << 2;
            *(float4*)&Bs[kk][c] = *(const float4*)(Wsrc + (size_t)(kb + kk) * C + c);
        }
        __syncthreads();
        #pragma unroll
        for (int kk = 0; kk < 16; kk++) {
            float a[8], b[8];
            *(float4*)&a[0] = *(const float4*)&As[kk][ty * 4];
            *(float4*)&a[4] = *(const float4*)&As[kk][64 + ty * 4];
            *(float4*)&b[0] = *(const float4*)&Bs[kk][tx * 4];
            *(float4*)&b[4] = *(const float4*)&Bs[kk][64 + tx * 4];
            #pragma unroll
            for (int i = 0; i < 8; i++)
                #pragma unroll
                for (int j = 0; j < 8; j++) acc[i][j] += a[i] * b[j];
        }
    }

    float bv[8];
    *(float4*)&bv[0] = *(const float4*)&bias[tx * 4];
    *(float4*)&bv[4] = *(const float4*)&bias[64 + tx * 4];
    #pragma unroll
    for (int i = 0; i < 8; i++) {
        int r = row0 + ((i < 4) ? (ty * 4 + i) : (64 + ty * 4 + i - 4));
        float4 o0 = make_float4(fmaxf(acc[i][0] + bv[0], 0.f), fmaxf(acc[i][1] + bv[1], 0.f),
                                fmaxf(acc[i][2] + bv[2], 0.f), fmaxf(acc[i][3] + bv[3], 0.f));
        float4 o1 = make_float4(fmaxf(acc[i][4] + bv[4], 0.f), fmaxf(acc[i][5] + bv[5], 0.f),
                                fmaxf(acc[i][6] + bv[6], 0.f), fmaxf(acc[i][7] + bv[7], 0.f));
        *(float4*)(g_h + (size_t)r * C + tx * 4) = o0;
        *(float4*)(g_h + (size_t)r * C + 64 + tx * 4) = o1;
    }
}

// ---------------- final: out[n] = h[n,:] . lin_w + lin_b ----------------
__global__ void k_dot(const float* __restrict__ lin_w, const float* __restrict__ lin_b,
                      float* __restrict__ out) {
    int n = (blockIdx.x * blockDim.x + threadIdx.x) >> 5;
    int lane = threadIdx.x & 31;
    if (n >= N_NODES) return;
    float4 v = *(const float4*)(g_h + (size_t)n * C + lane * 4);
    float4 w = *(const float4*)(lin_w + lane * 4);
    float s = v.x * w.x + v.y * w.y + v.z * w.z + v.w * w.w;
    #pragma unroll
    for (int o = 16; o; o >>= 1) s += __shfl_xor_sync(0xffffffffu, s, o);
    if (lane == 0) out[n] = s + lin_b[0];
}

// ---------------- launch ----------------
extern "C" void kernel_launch(void* const* d_in, const int* in_sizes, int n_in,
                              void* d_out, int out_size) {
    const float* x      = (const float*)d_in[0];
    const float* ew     = (const float*)d_in[1];
    const float* gamma  = (const float*)d_in[2];
    const float* beta   = (const float*)d_in[3];
    const float* Wself  = (const float*)d_in[4];
    const float* Wneigh = (const float*)d_in[5];
    const float* bias   = (const float*)d_in[6];
    const float* lin_w  = (const float*)d_in[7];
    const float* lin_b  = (const float*)d_in[8];
    const int*   src    = (const int*)d_in[9];
    const int*   dst    = (const int*)d_in[10];
    float*       out    = (float*)d_out;

    (void)in_sizes; (void)n_in; (void)out_size;

    k_prep0 <<<N_NODES / 256, 256>>>();
    k_count <<<N_EDGES / 256, 256>>>(dst);
    k_scan  <<<1, 1024>>>();
    k_scatter<<<N_EDGES / 256, 256>>>(src, dst, ew);

    for (int l = 0; l < L; l++) {
        k_stats<<<256, 256>>>(x, l);
        k_norm <<<512, 256>>>(x, gamma + l * C, beta + l * C, l);
        k_aggr <<<N_NODES * 32 / 256, 256>>>();
        k_gemm <<<N_NODES / 128, 256>>>(Wself + (size_t)l * C * C,
                                        Wneigh + (size_t)l * C * C,
                                        bias + (size_t)l * C);
    }
    k_dot<<<N_NODES * 32 / 256, 256>>>(lin_w, lin_b, out);
}

// round 3
// speedup vs baseline: 1.2841x; 1.2841x over previous
#include <cuda_runtime.h>
#include <cuda_bf16.h>
#include <math.h>
#include <stdint.h>

#define N_NODES 65536
#define N_EDGES 524288
#define C 128
#define L 3
#define BN_EPS 1e-5f

// ---------------- scratch (device globals; no dynamic allocation) ----------------
__device__ float  g_h[N_NODES * C];       // layer output
__device__ float  g_hn[N_NODES * C];      // batch-normalized activations
__device__ float  g_neigh[N_NODES * C];   // aggregated neighbor features (already /deg)
__device__ float2 g_edge[N_EDGES];        // CSR-by-dst packed records: (src bits, log1p(w))
__device__ int    g_degcnt[N_NODES];
__device__ int    g_off[N_NODES + 1];
__device__ int    g_cursor[N_NODES];
__device__ float  g_deginv[N_NODES];
__device__ float  g_stats[L * 2 * C];     // per-layer [sum(C) | sumsq(C)]
// pre-packed bf16 weight fragments in mma.sync per-lane order:
// [l][chunk][hilo][kstep(8)][nt16(16)][lane(32)] -> uint2 {b0, b1}
#define BPK_PER_CHUNK 8192                // 2 hilo * 8 kstep * 16 nt * 32 lane (uint2)
__device__ __align__(16) uint2 g_Bpk[L * 2 * BPK_PER_CHUNK];

// ---------------- helpers ----------------
__device__ __forceinline__ uint32_t pack_bf16x2(float lo, float hi) {
    // result.low16 = bf16(lo), result.high16 = bf16(hi)
    uint32_t r;
    asm("cvt.rn.bf16x2.f32 %0, %1, %2;" : "=r"(r) : "f"(hi), "f"(lo));
    return r;
}
// fp32 pair -> bf16x2 hi part + bf16x2 residual part
__device__ __forceinline__ void cvt_hilo(float2 v, uint32_t& hi, uint32_t& lo) {
    hi = pack_bf16x2(v.x, v.y);
    float f0 = __uint_as_float(hi << 16);
    float f1 = __uint_as_float(hi & 0xFFFF0000u);
    lo = pack_bf16x2(v.x - f0, v.y - f1);
}
__device__ __forceinline__ void mma_bf16(float* d, const uint32_t* a, uint32_t b0, uint32_t b1) {
    asm volatile(
        "mma.sync.aligned.m16n8k16.row.col.f32.bf16.bf16.f32 "
        "{%0,%1,%2,%3}, {%4,%5,%6,%7}, {%8,%9}, {%0,%1,%2,%3};"
        : "+f"(d[0]), "+f"(d[1]), "+f"(d[2]), "+f"(d[3])
        : "r"(a[0]), "r"(a[1]), "r"(a[2]), "r"(a[3]), "r"(b0), "r"(b1));
}

// ---------------- prep: zero counters/stats ----------------
__global__ void k_prep0() {
    int i = blockIdx.x * blockDim.x + threadIdx.x;
    if (i < N_NODES) g_degcnt[i] = 0;
    if (i < L * 2 * C) g_stats[i] = 0.0f;
}

// ---------------- prep: in-degree histogram ----------------
__global__ void k_count(const int* __restrict__ dst) {
    int e = blockIdx.x * blockDim.x + threadIdx.x;
    if (e < N_EDGES) atomicAdd(&g_degcnt[dst[e]], 1);
}

// ---------------- prep: exclusive scan over 65536 counts (single block) ----------------
__global__ void k_scan() {
    __shared__ int sp[1024];
    int t = threadIdx.x;
    int base = t * 64;
    int sum = 0;
    #pragma unroll 4
    for (int i = 0; i < 64; i++) sum += g_degcnt[base + i];
    sp[t] = sum;
    __syncthreads();
    for (int o = 1; o < 1024; o <<= 1) {
        int v = (t >= o) ? sp[t - o] : 0;
        __syncthreads();
        sp[t] += v;
        __syncthreads();
    }
    int run = sp[t] - sum;
    for (int i = 0; i < 64; i++) {
        int cnt = g_degcnt[base + i];
        g_off[base + i] = run;
        g_cursor[base + i] = run;
        g_deginv[base + i] = 1.0f / fmaxf((float)cnt, 1.0f);
        run += cnt;
    }
    if (t == 1023) g_off[N_NODES] = run;
}

// ---------------- prep: scatter edges into CSR order ----------------
__global__ void k_scatter(const int* __restrict__ src, const int* __restrict__ dst,
                          const float* __restrict__ ew) {
    int e = blockIdx.x * blockDim.x + threadIdx.x;
    if (e >= N_EDGES) return;
    int p = atomicAdd(&g_cursor[dst[e]], 1);
    g_edge[p] = make_float2(__int_as_float(src[e]), log1pf(ew[e]));
}

// ---------------- prep: weights -> pre-packed bf16 hi/lo mma fragments ----------------
// MMA computes D[m][n] = sum_k A[m][k] * B[k][n], B col fragment:
//   b0 = {B[k0][n], B[k0+1][n]},  b1 = {B[k0+8][n], B[k0+9][n]}
//   k0 = kstep*16 + (lane&3)*2,  n = nt*8 + (lane>>2);  B[k][n] = W[k*128 + n]
__global__ void k_wprep(const float* __restrict__ Ws, const float* __restrict__ Wn) {
    int i = blockIdx.x * blockDim.x + threadIdx.x;   // 49152 total
    if (i >= L * 2 * BPK_PER_CHUNK) return;
    int lane  = i & 31;
    int nt    = (i >> 5) & 15;
    int kstep = (i >> 9) & 7;
    int hilo  = (i >> 12) & 1;
    int chunk = (i >> 13) & 1;
    int l     = i >> 14;
    const float* W = (chunk ? Wn : Ws) + (size_t)l * 16384;
    int k0 = kstep * 16 + (lane & 3) * 2;
    int n  = nt * 8 + (lane >> 2);

    float v[4];
    v[0] = W[(k0 + 0) * 128 + n];
    v[1] = W[(k0 + 1) * 128 + n];
    v[2] = W[(k0 + 8) * 128 + n];
    v[3] = W[(k0 + 9) * 128 + n];
    uint32_t h0, l0, h1, l1;
    cvt_hilo(make_float2(v[0], v[1]), h0, l0);
    cvt_hilo(make_float2(v[2], v[3]), h1, l1);
    g_Bpk[i] = hilo ? make_uint2(l0, l1) : make_uint2(h0, h1);
}

// ---------------- per-layer: BN column sums ----------------
__global__ void k_stats(const float* __restrict__ x, int l) {
    const float* hp = (l == 0) ? x : g_h;
    int tid = threadIdx.x;
    int c = tid & (C - 1);
    int rr = tid >> 7;
    float s = 0.0f, s2 = 0.0f;
    for (int r = blockIdx.x * 2 + rr; r < N_NODES; r += gridDim.x * 2) {
        float v = hp[(size_t)r * C + c];
        s += v; s2 += v * v;
    }
    atomicAdd(&g_stats[l * 2 * C + c], s);
    atomicAdd(&g_stats[l * 2 * C + C + c], s2);
}

// ---------------- per-layer: normalize into g_hn ----------------
__global__ void k_norm(const float* __restrict__ x, const float* __restrict__ gamma,
                       const float* __restrict__ beta, int l) {
    __shared__ float sscale[C], sshift[C];
    const float* hp = (l == 0) ? x : g_h;
    int tid = threadIdx.x;
    if (tid < C) {
        float sum = g_stats[l * 2 * C + tid];
        float sq  = g_stats[l * 2 * C + C + tid];
        float mu  = sum * (1.0f / N_NODES);
        float var = sq * (1.0f / N_NODES) - mu * mu;
        float sc  = gamma[tid] * rsqrtf(var + BN_EPS);
        sscale[tid] = sc;
        sshift[tid] = beta[tid] - mu * sc;
    }
    __syncthreads();
    const float4* in4 = (const float4*)hp;
    float4* out4 = (float4*)g_hn;
    int total4 = N_NODES * C / 4;
    for (int i = blockIdx.x * blockDim.x + tid; i < total4; i += gridDim.x * blockDim.x) {
        int c4 = (i & 31) * 4;
        float4 v = in4[i];
        v.x = v.x * sscale[c4 + 0] + sshift[c4 + 0];
        v.y = v.y * sscale[c4 + 1] + sshift[c4 + 1];
        v.z = v.z * sscale[c4 + 2] + sshift[c4 + 2];
        v.w = v.w * sscale[c4 + 3] + sshift[c4 + 3];
        out4[i] = v;
    }
}

// ---------------- per-layer: mean aggregation, warp per node, no atomics ----------------
__global__ void k_aggr() {
    int n = (blockIdx.x * blockDim.x + threadIdx.x) >> 5;
    int lane = threadIdx.x & 31;
    if (n >= N_NODES) return;
    int beg = g_off[n], end = g_off[n + 1];
    const float4* hn4 = (const float4*)g_hn;
    float4 acc = make_float4(0.f, 0.f, 0.f, 0.f);
    for (int i = beg; i < end; i++) {
        float2 srw = g_edge[i];
        int s = __float_as_int(srw.x);
        float w = srw.y;
        float4 v = hn4[(size_t)s * 32 + lane];
        acc.x += w * v.x; acc.y += w * v.y; acc.z += w * v.z; acc.w += w * v.w;
    }
    float di = g_deginv[n];
    acc.x *= di; acc.y *= di; acc.z *= di; acc.w *= di;
    ((float4*)g_neigh)[(size_t)n * 32 + lane] = acc;
}

// ---------------- per-layer: mma.sync dual GEMM (3xBF16 split) + bias + ReLU ----------
// CTA 128x128 tile, 8 warps = 4(M) x 2(N), warp tile 32x64.
// D[m][n] = sum_k [hn|neigh][m][k] * [Ws;Wn][k][n], fp32 accum.
__global__ __launch_bounds__(256, 2)
void k_gemm(int l, const float* __restrict__ bias) {
    extern __shared__ uint2 sB[];          // 8192 uint2 = 64KB per chunk stage
    int tid = threadIdx.x, wid = tid >> 5, lane = tid & 31;
    int wm = wid >> 1, wn = wid & 1;
    int row0 = blockIdx.x * 128;

    float acc[2][8][4];
    #pragma unroll
    for (int mt = 0; mt < 2; mt++)
        #pragma unroll
        for (int nt = 0; nt < 8; nt++)
            #pragma unroll
            for (int q = 0; q < 4; q++) acc[mt][nt][q] = 0.0f;

    int ar = row0 + wm * 32 + (lane >> 2);   // A fragment base row
    int ak = (lane & 3) * 2;                 // A fragment base k (within kstep)

    for (int chunk = 0; chunk < 2; chunk++) {
        // stage this chunk's packed B fragments (hi+lo) into SMEM
        if (chunk) __syncthreads();          // protect sB reuse
        {
            const uint4* src = (const uint4*)(g_Bpk + ((size_t)(l * 2 + chunk)) * BPK_PER_CHUNK);
            uint4* dst = (uint4*)sB;
            #pragma unroll
            for (int it = 0; it < 16; it++) dst[it * 256 + tid] = src[it * 256 + tid];
        }
        __syncthreads();

        const float* Asrc = chunk ? g_neigh : g_hn;
        #pragma unroll 1
        for (int kstep = 0; kstep < 8; kstep++) {
            int kk = kstep * 16 + ak;
            uint32_t ahi[2][4], alo[2][4];
            #pragma unroll
            for (int mt = 0; mt < 2; mt++) {
                const float* p = Asrc + (size_t)(ar + mt * 16) * C + kk;
                cvt_hilo(*(const float2*)(p),             ahi[mt][0], alo[mt][0]);
                cvt_hilo(*(const float2*)(p + 8 * C),     ahi[mt][1], alo[mt][1]);
                cvt_hilo(*(const float2*)(p + 8),         ahi[mt][2], alo[mt][2]);
                cvt_hilo(*(const float2*)(p + 8 * C + 8), ahi[mt][3], alo[mt][3]);
            }
            #pragma unroll
            for (int nt = 0; nt < 8; nt++) {
                int ntg = wn * 8 + nt;
                uint2 bhi = sB[(kstep * 16 + ntg) * 32 + lane];
                uint2 blo = sB[4096 + (kstep * 16 + ntg) * 32 + lane];
                #pragma unroll
                for (int mt = 0; mt < 2; mt++) {
                    mma_bf16(acc[mt][nt], ahi[mt], bhi.x, bhi.y);
                    mma_bf16(acc[mt][nt], ahi[mt], blo.x, blo.y);
                    mma_bf16(acc[mt][nt], alo[mt], bhi.x, bhi.y);
                }
            }
        }
    }

    // epilogue: bias + ReLU, write fp32
    #pragma unroll
    for (int nt = 0; nt < 8; nt++) {
        int col = wn * 64 + nt * 8 + (lane & 3) * 2;
        float b0 = bias[col], b1 = bias[col + 1];
        #pragma unroll
        for (int mt = 0; mt < 2; mt++) {
            int r = ar + mt * 16;
            float2 o0 = make_float2(fmaxf(acc[mt][nt][0] + b0, 0.f),
                                    fmaxf(acc[mt][nt][1] + b1, 0.f));
            float2 o1 = make_float2(fmaxf(acc[mt][nt][2] + b0, 0.f),
                                    fmaxf(acc[mt][nt][3] + b1, 0.f));
            *(float2*)(g_h + (size_t)r * C + col)       = o0;
            *(float2*)(g_h + (size_t)(r + 8) * C + col) = o1;
        }
    }
}

// ---------------- final: out[n] = h[n,:] . lin_w + lin_b ----------------
__global__ void k_dot(const float* __restrict__ lin_w, const float* __restrict__ lin_b,
                      float* __restrict__ out) {
    int n = (blockIdx.x * blockDim.x + threadIdx.x) >> 5;
    int lane = threadIdx.x & 31;
    if (n >= N_NODES) return;
    float4 v = *(const float4*)(g_h + (size_t)n * C + lane * 4);
    float4 w = *(const float4*)(lin_w + lane * 4);
    float s = v.x * w.x + v.y * w.y + v.z * w.z + v.w * w.w;
    #pragma unroll
    for (int o = 16; o; o >>= 1) s += __shfl_xor_sync(0xffffffffu, s, o);
    if (lane == 0) out[n] = s + lin_b[0];
}

// ---------------- launch ----------------
#define GEMM_SMEM (8192 * 8)   // 64KB

extern "C" void kernel_launch(void* const* d_in, const int* in_sizes, int n_in,
                              void* d_out, int out_size) {
    const float* x      = (const float*)d_in[0];
    const float* ew     = (const float*)d_in[1];
    const float* gamma  = (const float*)d_in[2];
    const float* beta   = (const float*)d_in[3];
    const float* Wself  = (const float*)d_in[4];
    const float* Wneigh = (const float*)d_in[5];
    const float* bias   = (const float*)d_in[6];
    const float* lin_w  = (const float*)d_in[7];
    const float* lin_b  = (const float*)d_in[8];
    const int*   src    = (const int*)d_in[9];
    const int*   dst    = (const int*)d_in[10];
    float*       out    = (float*)d_out;

    (void)in_sizes; (void)n_in; (void)out_size;

    static int smem_set = 0;
    if (!smem_set) {
        cudaFuncSetAttribute(k_gemm, cudaFuncAttributeMaxDynamicSharedMemorySize, GEMM_SMEM);
        smem_set = 1;
    }

    k_prep0  <<<N_NODES / 256, 256>>>();
    k_count  <<<N_EDGES / 256, 256>>>(dst);
    k_scan   <<<1, 1024>>>();
    k_scatter<<<N_EDGES / 256, 256>>>(src, dst, ew);
    k_wprep  <<<(L * 2 * BPK_PER_CHUNK) / 256, 256>>>(Wself, Wneigh);

    for (int l = 0; l < L; l++) {
        k_stats<<<256, 256>>>(x, l);
        k_norm <<<512, 256>>>(x, gamma + l * C, beta + l * C, l);
        k_aggr <<<N_NODES * 32 / 256, 256>>>();
        k_gemm <<<N_NODES / 128, 256, GEMM_SMEM>>>(l, bias + (size_t)l * C);
    }
    k_dot<<<N_NODES * 32 / 256, 256>>>(lin_w, lin_b, out);
}

// round 6
// speedup vs baseline: 1.4510x; 1.1300x over previous
#include <cuda_runtime.h>
#include <cuda_bf16.h>
#include <math.h>
#include <stdint.h>

#define N_NODES 65536
#define N_EDGES 524288
#define C 128
#define L 3
#define BN_EPS 1e-5f

// ---------------- scratch (device globals; no dynamic allocation) ----------------
__device__ float  g_h[N_NODES * C];       // layer output (also layer input for l>0)
__device__ float  g_neigh[N_NODES * C];   // aggregated raw neighbor features (already /deg)
__device__ float  g_wbar[N_NODES];        // (sum of edge weights)/deg per node
__device__ float2 g_edge[N_EDGES];        // CSR-by-dst packed records: (src bits, log1p(w))
__device__ int    g_degcnt[N_NODES];
__device__ int    g_off[N_NODES + 1];
__device__ int    g_cursor[N_NODES];
__device__ float  g_deginv[N_NODES];
__device__ float  g_stats[L * 2 * C];     // per-layer [sum(C) | sumsq(C)]
__device__ float  g_scale[C];             // current layer BN scale (gamma * rsqrt(var+eps))
__device__ float  g_shift[C];             // current layer BN shift (beta - mu*scale)
// pre-packed bf16 weight fragments in mma.sync per-lane order:
// [l][chunk][hilo][kstep(8)][nt16(16)][lane(32)] -> uint2 {b0, b1}
#define BPK_PER_CHUNK 8192
__device__ __align__(16) uint2 g_Bpk[L * 2 * BPK_PER_CHUNK];

// ---------------- helpers ----------------
__device__ __forceinline__ uint32_t pack_bf16x2(float lo, float hi) {
    uint32_t r;
    asm("cvt.rn.bf16x2.f32 %0, %1, %2;" : "=r"(r) : "f"(hi), "f"(lo));
    return r;
}
__device__ __forceinline__ void cvt_hilo(float2 v, uint32_t& hi, uint32_t& lo) {
    hi = pack_bf16x2(v.x, v.y);
    float f0 = __uint_as_float(hi << 16);
    float f1 = __uint_as_float(hi & 0xFFFF0000u);
    lo = pack_bf16x2(v.x - f0, v.y - f1);
}
__device__ __forceinline__ void mma_bf16(float* d, const uint32_t* a, uint32_t b0, uint32_t b1) {
    asm volatile(
        "mma.sync.aligned.m16n8k16.row.col.f32.bf16.bf16.f32 "
        "{%0,%1,%2,%3}, {%4,%5,%6,%7}, {%8,%9}, {%0,%1,%2,%3};"
        : "+f"(d[0]), "+f"(d[1]), "+f"(d[2]), "+f"(d[3])
        : "r"(a[0]), "r"(a[1]), "r"(a[2]), "r"(a[3]), "r"(b0), "r"(b1));
}

// ---------------- prep ----------------
__global__ void k_prep0() {
    int i = blockIdx.x * blockDim.x + threadIdx.x;
    if (i < N_NODES) g_degcnt[i] = 0;
    if (i < L * 2 * C) g_stats[i] = 0.0f;
}
__global__ void k_count(const int* __restrict__ dst) {
    int e = blockIdx.x * blockDim.x + threadIdx.x;
    if (e < N_EDGES) atomicAdd(&g_degcnt[dst[e]], 1);
}
__global__ void k_scan() {
    __shared__ int sp[1024];
    int t = threadIdx.x;
    int base = t * 64;
    int sum = 0;
    #pragma unroll 4
    for (int i = 0; i < 64; i++) sum += g_degcnt[base + i];
    sp[t] = sum;
    __syncthreads();
    for (int o = 1; o < 1024; o <<= 1) {
        int v = (t >= o) ? sp[t - o] : 0;
        __syncthreads();
        sp[t] += v;
        __syncthreads();
    }
    int run = sp[t] - sum;
    for (int i = 0; i < 64; i++) {
        int cnt = g_degcnt[base + i];
        g_off[base + i] = run;
        g_cursor[base + i] = run;
        g_deginv[base + i] = 1.0f / fmaxf((float)cnt, 1.0f);
        run += cnt;
    }
    if (t == 1023) g_off[N_NODES] = run;
}
__global__ void k_scatter(const int* __restrict__ src, const int* __restrict__ dst,
                          const float* __restrict__ ew) {
    int e = blockIdx.x * blockDim.x + threadIdx.x;
    if (e >= N_EDGES) return;
    int p = atomicAdd(&g_cursor[dst[e]], 1);
    g_edge[p] = make_float2(__int_as_float(src[e]), log1pf(ew[e]));
}

// ---------------- prep: weights -> pre-packed bf16 hi/lo mma fragments ----------------
__global__ void k_wprep(const float* __restrict__ Ws, const float* __restrict__ Wn) {
    int i = blockIdx.x * blockDim.x + threadIdx.x;
    if (i >= L * 2 * BPK_PER_CHUNK) return;
    int lane  = i & 31;
    int nt    = (i >> 5) & 15;
    int kstep = (i >> 9) & 7;
    int hilo  = (i >> 12) & 1;
    int chunk = (i >> 13) & 1;
    int l     = i >> 14;
    const float* W = (chunk ? Wn : Ws) + (size_t)l * 16384;
    int k0 = kstep * 16 + (lane & 3) * 2;
    int n  = nt * 8 + (lane >> 2);
    float v0 = W[(k0 + 0) * 128 + n], v1 = W[(k0 + 1) * 128 + n];
    float v2 = W[(k0 + 8) * 128 + n], v3 = W[(k0 + 9) * 128 + n];
    uint32_t h0, l0, h1, l1;
    cvt_hilo(make_float2(v0, v1), h0, l0);
    cvt_hilo(make_float2(v2, v3), h1, l1);
    g_Bpk[i] = hilo ? make_uint2(l0, l1) : make_uint2(h0, h1);
}

// ---------------- one-time: BN column stats of x (layer 0) ----------------
__global__ void k_stats(const float* __restrict__ x) {
    int tid = threadIdx.x;
    int c = tid & (C - 1);
    int rr = tid >> 7;
    float s = 0.0f, s2 = 0.0f;
    for (int r = blockIdx.x * 2 + rr; r < N_NODES; r += gridDim.x * 2) {
        float v = x[(size_t)r * C + c];
        s += v; s2 += v * v;
    }
    atomicAdd(&g_stats[c], s);
    atomicAdd(&g_stats[C + c], s2);
}

// ---------------- per-layer: BN affine coefficients ----------------
__global__ void k_coef(int l, const float* __restrict__ gamma, const float* __restrict__ beta) {
    int c = threadIdx.x;  // 128
    float sum = g_stats[l * 2 * C + c];
    float sq  = g_stats[l * 2 * C + C + c];
    float mu  = sum * (1.0f / N_NODES);
    float var = sq * (1.0f / N_NODES) - mu * mu;
    float sc  = gamma[l * C + c] * rsqrtf(var + BN_EPS);
    g_scale[c] = sc;
    g_shift[c] = beta[l * C + c] - mu * sc;
}

// ---------------- per-layer: raw mean aggregation + wbar, 4x unrolled gathers -------
__global__ void k_aggr(const float* __restrict__ in) {
    int n = (blockIdx.x * blockDim.x + threadIdx.x) >> 5;
    int lane = threadIdx.x & 31;
    if (n >= N_NODES) return;
    int beg = g_off[n], end = g_off[n + 1];
    const float4* in4 = (const float4*)in;
    float4 a0 = make_float4(0.f, 0.f, 0.f, 0.f);
    float4 a1 = make_float4(0.f, 0.f, 0.f, 0.f);
    float ws = 0.f;
    int i = beg;
    for (; i + 4 <= end; i += 4) {
        float2 e0 = g_edge[i],     e1 = g_edge[i + 1];
        float2 e2 = g_edge[i + 2], e3 = g_edge[i + 3];
        float4 v0 = __ldg(&in4[(size_t)__float_as_int(e0.x) * 32 + lane]);
        float4 v1 = __ldg(&in4[(size_t)__float_as_int(e1.x) * 32 + lane]);
        float4 v2 = __ldg(&in4[(size_t)__float_as_int(e2.x) * 32 + lane]);
        float4 v3 = __ldg(&in4[(size_t)__float_as_int(e3.x) * 32 + lane]);
        a0.x += e0.y * v0.x; a0.y += e0.y * v0.y; a0.z += e0.y * v0.z; a0.w += e0.y * v0.w;
        a1.x += e1.y * v1.x; a1.y += e1.y * v1.y; a1.z += e1.y * v1.z; a1.w += e1.y * v1.w;
        a0.x += e2.y * v2.x; a0.y += e2.y * v2.y; a0.z += e2.y * v2.z; a0.w += e2.y * v2.w;
        a1.x += e3.y * v3.x; a1.y += e3.y * v3.y; a1.z += e3.y * v3.z; a1.w += e3.y * v3.w;
        ws += (e0.y + e1.y) + (e2.y + e3.y);
    }
    for (; i < end; i++) {
        float2 e = g_edge[i];
        float4 v = __ldg(&in4[(size_t)__float_as_int(e.x) * 32 + lane]);
        a0.x += e.y * v.x; a0.y += e.y * v.y; a0.z += e.y * v.z; a0.w += e.y * v.w;
        ws += e.y;
    }
    float di = g_deginv[n];
    float4 acc = make_float4((a0.x + a1.x) * di, (a0.y + a1.y) * di,
                             (a0.z + a1.z) * di, (a0.w + a1.w) * di);
    ((float4*)g_neigh)[(size_t)n * 32 + lane] = acc;
    if (lane == 0) g_wbar[n] = ws * di;
}

// ---------------- per-layer: mma.sync dual GEMM with fused BN affine + stats --------
// A0 = sc*in + sh (normalized h); A1 = sc*neigh_raw + sh*wbar (normalized aggregate).
// D = A0 @ Ws + A1 @ Wn + bias, ReLU; epilogue also accumulates next-layer BN stats.
// smem: 65536 (sB) + 512 (sSc) + 512 (sSh) + 1024 (sStat) = 67584
#define GEMM_SMEM (65536 + 2048)

__global__ __launch_bounds__(256, 2)
void k_gemm(int l, const float* __restrict__ Ain, const float* __restrict__ bias,
            int do_stats) {
    extern __shared__ unsigned char dyn[];
    uint2* sB    = (uint2*)dyn;                       // 64KB: packed B fragments (hi+lo)
    float* sSc   = (float*)(dyn + 65536);             // 128 scale
    float* sSh   = sSc + 128;                         // 128 shift
    float* sStat = sSh + 128;                         // 256: col sums | col sumsq

    int tid = threadIdx.x, wid = tid >> 5, lane = tid & 31;
    int wm = wid >> 1, wn = wid & 1;
    int row0 = blockIdx.x * 128;

    if (tid < 128) { sSc[tid] = g_scale[tid]; sSh[tid] = g_shift[tid]; }
    if (tid < 256) sStat[tid] = 0.0f;

    float acc[2][8][4];
    #pragma unroll
    for (int mt = 0; mt < 2; mt++)
        #pragma unroll
        for (int nt = 0; nt < 8; nt++)
            #pragma unroll
            for (int q = 0; q < 4; q++) acc[mt][nt][q] = 0.0f;

    int ar = row0 + wm * 32 + (lane >> 2);
    int ak = (lane & 3) * 2;
    // per-row wbar (only used for chunk 1)
    float wb[2][2];
    #pragma unroll
    for (int mt = 0; mt < 2; mt++) {
        wb[mt][0] = g_wbar[ar + mt * 16];
        wb[mt][1] = g_wbar[ar + mt * 16 + 8];
    }

    #pragma unroll
    for (int chunk = 0; chunk < 2; chunk++) {
        if (chunk) __syncthreads();
        {
            const uint4* src = (const uint4*)(g_Bpk + ((size_t)(l * 2 + chunk)) * BPK_PER_CHUNK);
            uint4* dst = (uint4*)sB;
            #pragma unroll
            for (int it = 0; it < 16; it++) dst[it * 256 + tid] = src[it * 256 + tid];
        }
        __syncthreads();

        const float* Asrc = chunk ? g_neigh : Ain;
        #pragma unroll 1
        for (int kstep = 0; kstep < 8; kstep++) {
            int kk = kstep * 16 + ak;
            float2 sc01 = *(const float2*)&sSc[kk];
            float2 sc89 = *(const float2*)&sSc[kk + 8];
            float2 sh01 = *(const float2*)&sSh[kk];
            float2 sh89 = *(const float2*)&sSh[kk + 8];
            uint32_t ahi[2][4], alo[2][4];
            #pragma unroll
            for (int mt = 0; mt < 2; mt++) {
                float m0 = chunk ? wb[mt][0] : 1.0f;
                float m1 = chunk ? wb[mt][1] : 1.0f;
                const float* p = Asrc + (size_t)(ar + mt * 16) * C + kk;
                float2 v;
                v = *(const float2*)(p);
                v.x = v.x * sc01.x + sh01.x * m0; v.y = v.y * sc01.y + sh01.y * m0;
                cvt_hilo(v, ahi[mt][0], alo[mt][0]);
                v = *(const float2*)(p + 8 * C);
                v.x = v.x * sc01.x + sh01.x * m1; v.y = v.y * sc01.y + sh01.y * m1;
                cvt_hilo(v, ahi[mt][1], alo[mt][1]);
                v = *(const float2*)(p + 8);
                v.x = v.x * sc89.x + sh89.x * m0; v.y = v.y * sc89.y + sh89.y * m0;
                cvt_hilo(v, ahi[mt][2], alo[mt][2]);
                v = *(const float2*)(p + 8 * C + 8);
                v.x = v.x * sc89.x + sh89.x * m1; v.y = v.y * sc89.y + sh89.y * m1;
                cvt_hilo(v, ahi[mt][3], alo[mt][3]);
            }
            #pragma unroll
            for (int nt = 0; nt < 8; nt++) {
                int ntg = wn * 8 + nt;
                uint2 bhi = sB[(kstep * 16 + ntg) * 32 + lane];
                uint2 blo = sB[4096 + (kstep * 16 + ntg) * 32 + lane];
                #pragma unroll
                for (int mt = 0; mt < 2; mt++) {
                    mma_bf16(acc[mt][nt], ahi[mt], bhi.x, bhi.y);
                    mma_bf16(acc[mt][nt], ahi[mt], blo.x, blo.y);
                    mma_bf16(acc[mt][nt], alo[mt], bhi.x, bhi.y);
                }
            }
        }
    }

    // epilogue: bias + ReLU, write, accumulate next-layer BN stats
    #pragma unroll
    for (int nt = 0; nt < 8; nt++) {
        int col = wn * 64 + nt * 8 + (lane & 3) * 2;
        float b0 = bias[col], b1 = bias[col + 1];
        float s0 = 0.f, s1 = 0.f, q0 = 0.f, q1 = 0.f;
        #pragma unroll
        for (int mt = 0; mt < 2; mt++) {
            int r = ar + mt * 16;
            float o00 = fmaxf(acc[mt][nt][0] + b0, 0.f);
            float o01 = fmaxf(acc[mt][nt][1] + b1, 0.f);
            float o10 = fmaxf(acc[mt][nt][2] + b0, 0.f);
            float o11 = fmaxf(acc[mt][nt][3] + b1, 0.f);
            *(float2*)(g_h + (size_t)r * C + col)       = make_float2(o00, o01);
            *(float2*)(g_h + (size_t)(r + 8) * C + col) = make_float2(o10, o11);
            s0 += o00 + o10; s1 += o01 + o11;
            q0 += o00 * o00 + o10 * o10; q1 += o01 * o01 + o11 * o11;
        }
        if (do_stats) {
            #pragma unroll
            for (int off = 16; off >= 4; off >>= 1) {
                s0 += __shfl_down_sync(0xffffffffu, s0, off);
                s1 += __shfl_down_sync(0xffffffffu, s1, off);
                q0 += __shfl_down_sync(0xffffffffu, q0, off);
                q1 += __shfl_down_sync(0xffffffffu, q1, off);
            }
            if (lane < 4) {
                atomicAdd(&sStat[col],           s0);
                atomicAdd(&sStat[col + 1],       s1);
                atomicAdd(&sStat[128 + col],     q0);
                atomicAdd(&sStat[128 + col + 1], q1);
            }
        }
    }
    if (do_stats) {
        __syncthreads();
        if (tid < 128) {
            atomicAdd(&g_stats[(l + 1) * 2 * C + tid],     sStat[tid]);
            atomicAdd(&g_stats[(l + 1) * 2 * C + C + tid], sStat[128 + tid]);
        }
    }
}

// ---------------- final: out[n] = h[n,:] . lin_w + lin_b ----------------
__global__ void k_dot(const float* __restrict__ lin_w, const float* __restrict__ lin_b,
                      float* __restrict__ out) {
    int n = (blockIdx.x * blockDim.x + threadIdx.x) >> 5;
    int lane = threadIdx.x & 31;
    if (n >= N_NODES) return;
    float4 v = *(const float4*)(g_h + (size_t)n * C + lane * 4);
    float4 w = *(const float4*)(lin_w + lane * 4);
    float s = v.x * w.x + v.y * w.y + v.z * w.z + v.w * w.w;
    #pragma unroll
    for (int o = 16; o; o >>= 1) s += __shfl_xor_sync(0xffffffffu, s, o);
    if (lane == 0) out[n] = s + lin_b[0];
}

// ---------------- launch ----------------
extern "C" void kernel_launch(void* const* d_in, const int* in_sizes, int n_in,
                              void* d_out, int out_size) {
    const float* x      = (const float*)d_in[0];
    const float* ew     = (const float*)d_in[1];
    const float* gamma  = (const float*)d_in[2];
    const float* beta   = (const float*)d_in[3];
    const float* Wself  = (const float*)d_in[4];
    const float* Wneigh = (const float*)d_in[5];
    const float* bias   = (const float*)d_in[6];
    const float* lin_w  = (const float*)d_in[7];
    const float* lin_b  = (const float*)d_in[8];
    const int*   src    = (const int*)d_in[9];
    const int*   dst    = (const int*)d_in[10];
    float*       out    = (float*)d_out;

    (void)in_sizes; (void)n_in; (void)out_size;

    cudaFuncSetAttribute(k_gemm, cudaFuncAttributeMaxDynamicSharedMemorySize, GEMM_SMEM);

    float* hdev = nullptr;
    cudaGetSymbolAddress((void**)&hdev, g_h);

    k_prep0  <<<N_NODES / 256, 256>>>();
    k_count  <<<N_EDGES / 256, 256>>>(dst);
    k_scan   <<<1, 1024>>>();
    k_scatter<<<N_EDGES / 256, 256>>>(src, dst, ew);
    k_wprep  <<<(L * 2 * BPK_PER_CHUNK) / 256, 256>>>(Wself, Wneigh);
    k_stats  <<<256, 256>>>(x);

    for (int l = 0; l < L; l++) {
        const float* in = (l == 0) ? x : hdev;
        k_coef<<<1, 128>>>(l, gamma, beta);
        k_aggr<<<N_NODES * 32 / 256, 256>>>(in);
        k_gemm<<<N_NODES / 128, 256, GEMM_SMEM>>>(l, in, bias + (size_t)l * C,
                                                  (l < L - 1) ? 1 : 0);
    }
    k_dot<<<N_NODES * 32 / 256, 256>>>(lin_w, lin_b, out);
}